// round 4
// baseline (speedup 1.0000x reference)
#include <cuda_runtime.h>

#define NMAX   10000
#define EMAX   160000
#define ELMAX  (EMAX + NMAX)
#define HIDD   128
#define NH     4
#define HC     512          // NH * 128
#define NF     5
#define BMAX   64
#define CAP    256          // max cached in-degree for shared alpha
#define RPB    32           // rows per block in projection

// ---------------- scratch (static device globals; no allocation) -------------
__device__ float g_h[NMAX * HIDD];       // current node features
__device__ float g_hp[NMAX * HC];        // per-layer projection [N,H,C]
__device__ float g_asrc[NMAX * NH];
__device__ float g_adst[NMAX * NH];
__device__ int   g_deg[NMAX];
__device__ int   g_off[NMAX + 1];
__device__ int   g_cur[NMAX];
__device__ int   g_srcs[ELMAX];          // CSR-by-dst: source node ids
__device__ int   g_cnt[BMAX];

// ---------------- f32x2 helpers ----------------------------------------------
__device__ __forceinline__ unsigned long long pk2(float x, float y) {
    unsigned long long r;
    asm("mov.b64 %0, {%1, %2};" : "=l"(r) : "f"(x), "f"(y));
    return r;
}
__device__ __forceinline__ void fma2(unsigned long long& d,
                                     unsigned long long a, unsigned long long b) {
    asm("fma.rn.f32x2 %0, %1, %2, %0;" : "+l"(d) : "l"(a), "l"(b));
}
__device__ __forceinline__ float fold2(unsigned long long v) {
    float lo, hi;
    asm("mov.b64 {%0, %1}, %2;" : "=f"(lo), "=f"(hi) : "l"(v));
    return lo + hi;
}

// ---------------- CSR build --------------------------------------------------
__global__ void zero_deg_kernel(int N) {
    int i = blockIdx.x * blockDim.x + threadIdx.x;
    if (i < N) g_deg[i] = 0;
}

__global__ void count_kernel(const int* __restrict__ ei, int E, int N) {
    int i = blockIdx.x * blockDim.x + threadIdx.x;
    int EL = E + N;
    if (i >= EL) return;
    int dst = (i < E) ? ei[E + i] : (i - E);   // self-loops appended
    atomicAdd(&g_deg[dst], 1);
}

__global__ void scan_kernel(int N) {
    __shared__ int wsum[32];
    int tid  = threadIdx.x;              // 1024 threads
    int lane = tid & 31, w = tid >> 5;
    int CH   = (N + 1023) >> 10;
    int base = tid * CH;

    int s = 0;
    for (int k = 0; k < CH; k++) {
        int idx = base + k;
        if (idx < N) s += g_deg[idx];
    }
    int v = s;
    #pragma unroll
    for (int o = 1; o < 32; o <<= 1) {
        int t = __shfl_up_sync(0xffffffffu, v, o);
        if (lane >= o) v += t;
    }
    if (lane == 31) wsum[w] = v;
    __syncthreads();
    if (w == 0) {
        int t = wsum[lane];
        #pragma unroll
        for (int o = 1; o < 32; o <<= 1) {
            int u = __shfl_up_sync(0xffffffffu, t, o);
            if (lane >= o) t += u;
        }
        wsum[lane] = t;
    }
    __syncthreads();
    int excl = v - s + ((w > 0) ? wsum[w - 1] : 0);
    int run  = excl;
    for (int k = 0; k < CH; k++) {
        int idx = base + k;
        if (idx < N) {
            g_off[idx] = run;
            g_cur[idx] = run;
            run += g_deg[idx];
        }
    }
    if (tid == 1023) g_off[N] = wsum[31];
}

__global__ void scatter_kernel(const int* __restrict__ ei, int E, int N) {
    int i = blockIdx.x * blockDim.x + threadIdx.x;
    int EL = E + N;
    if (i >= EL) return;
    int src, dst;
    if (i < E) { src = ei[i]; dst = ei[E + i]; }
    else       { src = i - E; dst = i - E; }
    int p = atomicAdd(&g_cur[dst], 1);
    g_srcs[p] = src;
}

// ---------------- node encoder: h = relu(x @ node_W + node_b) ----------------
__global__ void init_kernel(const float* __restrict__ x,
                            const float* __restrict__ W,
                            const float* __restrict__ b, int N) {
    int n = blockIdx.x;
    int j = threadIdx.x;
    float acc = b[j];
    #pragma unroll
    for (int k = 0; k < NF; k++)
        acc += x[n * NF + k] * W[k * HIDD + j];
    g_h[n * HIDD + j] = fmaxf(acc, 0.f);
}

// ------- fused projection + attention scalars (FFMA2 mainloop) ---------------
// block: (RPB rows) x (head blockIdx.y, 128 cols). hp = h @ W chunk with packed
// f32x2 FMAs (even/odd-k partial sums per row), then a_src/a_dst for this head
// via an smem transpose of the accumulators.
__global__ void __launch_bounds__(128) proj_att_kernel(
        const float* __restrict__ W,
        const float* __restrict__ att_s,
        const float* __restrict__ att_d, int N) {
    __shared__ float sh[RPB * HIDD];        // 16 KB: h rows, later acc transpose
    __shared__ float s_att[2 * HIDD];       // att_s | att_d for this head
    __shared__ float s_red[2][4][RPB];      // quarter partials (src, dst)
    int tid = threadIdx.x, lane = tid & 31;
    int n0 = blockIdx.x * RPB;
    int hy = blockIdx.y;
    int col = hy * 128 + tid;

    // cooperative load of RPB rows of h (float4) + att vectors
    for (int t = tid; t < RPB * (HIDD / 4); t += 128) {
        int n = n0 + t / (HIDD / 4);
        float4 v = make_float4(0.f, 0.f, 0.f, 0.f);
        if (n < N) v = ((const float4*)g_h)[(size_t)n * (HIDD / 4) + t % (HIDD / 4)];
        ((float4*)sh)[t] = v;
    }
    s_att[tid]        = att_s[hy * 128 + tid];
    s_att[HIDD + tid] = att_d[hy * 128 + tid];
    __syncthreads();

    unsigned long long accp[RPB];
    #pragma unroll
    for (int i = 0; i < RPB; i++) accp[i] = 0ull;

    const ulonglong2* shp = (const ulonglong2*)sh;   // row stride = 32 ulonglong2
    #pragma unroll 2
    for (int k4 = 0; k4 < HIDD / 4; k4++) {
        int k = k4 * 4;
        float w0 = W[(k + 0) * HC + col];
        float w1 = W[(k + 1) * HC + col];
        float w2 = W[(k + 2) * HC + col];
        float w3 = W[(k + 3) * HC + col];
        unsigned long long b0 = pk2(w0, w1);
        unsigned long long b1 = pk2(w2, w3);
        #pragma unroll
        for (int i = 0; i < RPB; i++) {
            ulonglong2 a = shp[i * (HIDD / 4 / 2 * 1) * 1 + k4 + i * 0];  // placeholder
            // real index: row i occupies 32 ulonglong2 (512B)
            a = shp[i * 32 + k4];
            fma2(accp[i], a.x, b0);
            fma2(accp[i], a.y, b1);
        }
    }

    float acc[RPB];
    #pragma unroll
    for (int i = 0; i < RPB; i++) acc[i] = fold2(accp[i]);

    // store hp
    #pragma unroll
    for (int i = 0; i < RPB; i++) {
        int n = n0 + i;
        if (n < N) g_hp[(size_t)n * HC + col] = acc[i];
    }

    // ---- attention scalars via smem transpose (all reads of sh are done) ----
    __syncthreads();
    #pragma unroll
    for (int i = 0; i < RPB; i++) sh[i * HIDD + tid] = acc[i];
    __syncthreads();

    {
        int r = tid & 31;            // row within tile
        int q = tid >> 5;            // column quarter
        const float* rowp = sh + r * HIDD + q * 32;
        const float* asq  = s_att + q * 32;
        const float* adq  = s_att + HIDD + q * 32;
        float ps = 0.f, pd = 0.f;
        #pragma unroll
        for (int c = 0; c < 32; c++) {
            float v = rowp[c];
            ps += v * asq[c];
            pd += v * adq[c];
        }
        s_red[0][q][r] = ps;
        s_red[1][q][r] = pd;
    }
    __syncthreads();
    if (tid < RPB && n0 + tid < N) {
        g_asrc[(n0 + tid) * NH + hy] =
            s_red[0][0][tid] + s_red[0][1][tid] + s_red[0][2][tid] + s_red[0][3][tid];
        g_adst[(n0 + tid) * NH + hy] =
            s_red[1][0][tid] + s_red[1][1][tid] + s_red[1][2][tid] + s_red[1][3][tid];
    }
}

// ---------------- fused: softmax + aggregate + head-mean + LN + relu + resid -
__global__ void agg_kernel(const float* __restrict__ bias,
                           const float* __restrict__ lng,
                           const float* __restrict__ lnb, int N) {
    int n = blockIdx.x;
    int tid = threadIdx.x, lane = tid & 31, w = tid >> 5;
    __shared__ float s_alpha[CAP * NH];
    __shared__ int   s_src[CAP];
    __shared__ float s_m[NH], s_d[NH];
    __shared__ float s_tr[HC];
    __shared__ float s_r1[NH], s_r2[NH];

    int beg = g_off[n], end = g_off[n + 1];
    int deg = end - beg;
    int cd  = (deg < CAP) ? deg : CAP;

    for (int li = tid; li < cd; li += 128) s_src[li] = g_srcs[beg + li];
    __syncthreads();

    // per-warp (head w) softmax max + sum; cache unnormalized weights
    float ad = g_adst[n * NH + w];
    float mx = -1e30f;
    for (int li = lane; li < deg; li += 32) {
        int s = (li < CAP) ? s_src[li] : g_srcs[beg + li];
        float e = g_asrc[s * NH + w] + ad;
        e = (e > 0.f) ? e : 0.2f * e;
        mx = fmaxf(mx, e);
    }
    #pragma unroll
    for (int o = 16; o; o >>= 1) mx = fmaxf(mx, __shfl_xor_sync(0xffffffffu, mx, o));
    float sum = 0.f;
    for (int li = lane; li < deg; li += 32) {
        int s = (li < CAP) ? s_src[li] : g_srcs[beg + li];
        float e = g_asrc[s * NH + w] + ad;
        e = (e > 0.f) ? e : 0.2f * e;
        float ex = __expf(e - mx);
        sum += ex;
        if (li < CAP) s_alpha[li * NH + w] = ex;
    }
    #pragma unroll
    for (int o = 16; o; o >>= 1) sum += __shfl_xor_sync(0xffffffffu, sum, o);
    if (lane == 0) { s_m[w] = mx; s_d[w] = sum; }
    __syncthreads();

    // aggregate: thread tid owns flat channels 4*tid..4*tid+3 (head w,
    // channels 4*lane..4*lane+3). One LDG.128 per thread per edge, 4-deep.
    const float* base = g_hp + 4 * tid;
    float ax = 0.f, ay = 0.f, az = 0.f, aw = 0.f;
    int li = 0;
    for (; li + 4 <= cd; li += 4) {
        int s0 = s_src[li], s1 = s_src[li + 1], s2 = s_src[li + 2], s3 = s_src[li + 3];
        float4 r0 = *(const float4*)(base + (size_t)s0 * HC);
        float4 r1 = *(const float4*)(base + (size_t)s1 * HC);
        float4 r2 = *(const float4*)(base + (size_t)s2 * HC);
        float4 r3 = *(const float4*)(base + (size_t)s3 * HC);
        float w0 = s_alpha[li * NH + w];
        float w1 = s_alpha[(li + 1) * NH + w];
        float w2 = s_alpha[(li + 2) * NH + w];
        float w3 = s_alpha[(li + 3) * NH + w];
        ax += w0 * r0.x + w1 * r1.x + w2 * r2.x + w3 * r3.x;
        ay += w0 * r0.y + w1 * r1.y + w2 * r2.y + w3 * r3.y;
        az += w0 * r0.z + w1 * r1.z + w2 * r2.z + w3 * r3.z;
        aw += w0 * r0.w + w1 * r1.w + w2 * r2.w + w3 * r3.w;
    }
    for (; li < cd; ++li) {
        int s0 = s_src[li];
        float4 r0 = *(const float4*)(base + (size_t)s0 * HC);
        float w0 = s_alpha[li * NH + w];
        ax += w0 * r0.x; ay += w0 * r0.y; az += w0 * r0.z; aw += w0 * r0.w;
    }
    // rare fallback: in-degree beyond CAP, recompute ex on the fly
    for (int i2 = beg + CAP; i2 < end; ++i2) {
        int s = g_srcs[i2];
        float e = g_asrc[s * NH + w] + ad;
        e = (e > 0.f) ? e : 0.2f * e;
        float ex = __expf(e - s_m[w]);
        float4 r0 = *(const float4*)(base + (size_t)s * HC);
        ax += ex * r0.x; ay += ex * r0.y; az += ex * r0.z; aw += ex * r0.w;
    }

    float inv = 1.f / (s_d[w] + 1e-16f);
    float4 o4 = make_float4(ax * inv, ay * inv, az * inv, aw * inv);
    ((float4*)s_tr)[tid] = o4;
    __syncthreads();

    // head mean (transpose via shared) + bias
    int c = tid;
    float v = 0.25f * (s_tr[c] + s_tr[128 + c] + s_tr[256 + c] + s_tr[384 + c])
              + bias[c];

    // LayerNorm over 128 channels
    float t = v;
    #pragma unroll
    for (int o = 16; o; o >>= 1) t += __shfl_xor_sync(0xffffffffu, t, o);
    if (lane == 0) s_r1[w] = t;
    __syncthreads();
    float mu = (s_r1[0] + s_r1[1] + s_r1[2] + s_r1[3]) * (1.f / 128.f);
    float dv = v - mu;
    float t2 = dv * dv;
    #pragma unroll
    for (int o = 16; o; o >>= 1) t2 += __shfl_xor_sync(0xffffffffu, t2, o);
    if (lane == 0) s_r2[w] = t2;
    __syncthreads();
    float var = (s_r2[0] + s_r2[1] + s_r2[2] + s_r2[3]) * (1.f / 128.f);
    float y = dv * rsqrtf(var + 1e-5f) * lng[c] + lnb[c];

    g_h[n * HIDD + c] = fmaxf(y, 0.f) + g_h[n * HIDD + c];
}

// ---------------- pooling ----------------------------------------------------
__global__ void zero_pool_kernel(float* __restrict__ out, int N, int B) {
    int i = blockIdx.x * blockDim.x + threadIdx.x;
    if (i < B * HIDD) out[N * HIDD + i] = 0.f;
    if (i < B) g_cnt[i] = 0;
}

__global__ void pool_sum_kernel(const int* __restrict__ batch,
                                float* __restrict__ out, int N) {
    int n = blockIdx.x;
    int j = threadIdx.x;
    float v = g_h[n * HIDD + j];
    out[n * HIDD + j] = v;                       // copy h to output
    int b = batch[n];
    atomicAdd(&out[N * HIDD + b * HIDD + j], v);
    if (j == 0) atomicAdd(&g_cnt[b], 1);
}

__global__ void pool_div_kernel(float* __restrict__ out, int N) {
    int b = blockIdx.x;
    int j = threadIdx.x;
    float c = (float)max(g_cnt[b], 1);
    out[N * HIDD + b * HIDD + j] *= (1.f / c);
}

// ---------------- launch -----------------------------------------------------
extern "C" void kernel_launch(void* const* d_in, const int* in_sizes, int n_in,
                              void* d_out, int out_size) {
    const float* x        = (const float*)d_in[0];
    const int*   ei       = (const int*)d_in[1];   // [2,E] int32
    const int*   batch    = (const int*)d_in[2];
    const float* node_W   = (const float*)d_in[3];
    const float* node_b   = (const float*)d_in[4];
    const float* Ws       = (const float*)d_in[5];
    const float* att_srcs = (const float*)d_in[6];
    const float* att_dsts = (const float*)d_in[7];
    const float* biases   = (const float*)d_in[8];
    const float* ln_gs    = (const float*)d_in[9];
    const float* ln_bs    = (const float*)d_in[10];
    float* out = (float*)d_out;

    int N  = in_sizes[0] / NF;
    int E  = in_sizes[1] / 2;
    int B  = out_size / HIDD - N;
    int L  = in_sizes[5] / (HIDD * HC);
    int EL = E + N;

    zero_deg_kernel<<<(N + 255) / 256, 256>>>(N);
    count_kernel<<<(EL + 255) / 256, 256>>>(ei, E, N);
    scan_kernel<<<1, 1024>>>(N);
    scatter_kernel<<<(EL + 255) / 256, 256>>>(ei, E, N);

    init_kernel<<<N, HIDD>>>(x, node_W, node_b, N);

    for (int l = 0; l < L; l++) {
        proj_att_kernel<<<dim3((N + RPB - 1) / RPB, NH), 128>>>(
            Ws + (size_t)l * HIDD * HC,
            att_srcs + l * NH * 128, att_dsts + l * NH * 128, N);
        agg_kernel<<<N, 128>>>(biases + l * HIDD, ln_gs + l * HIDD, ln_bs + l * HIDD, N);
    }

    zero_pool_kernel<<<(B * HIDD + 255) / 256, 256>>>(out, N, B);
    pool_sum_kernel<<<N, HIDD>>>(batch, out, N);
    pool_div_kernel<<<B, HIDD>>>(out, N);
}

// round 5
// speedup vs baseline: 1.1298x; 1.1298x over previous
#include <cuda_runtime.h>

#define NMAX   10000
#define EMAX   160000
#define ELMAX  (EMAX + NMAX)
#define HIDD   128
#define NH     4
#define HC     512          // NH * 128
#define NF     5
#define BMAX   64
#define CAP    256          // max cached in-degree for shared alpha
#define RPB    32           // rows per block in projection

// ---------------- scratch (static device globals; no allocation) -------------
__device__ float g_h[NMAX * HIDD];       // current node features
__device__ float g_hp[NMAX * HC];        // per-layer projection [N,H,C]
__device__ float g_asrc[NMAX * NH];
__device__ float g_adst[NMAX * NH];
__device__ int   g_deg[NMAX];
__device__ int   g_off[NMAX + 1];
__device__ int   g_cur[NMAX];
__device__ int   g_srcs[ELMAX];          // CSR-by-dst: source node ids
__device__ int   g_cnt[BMAX];

// ---------------- CSR build --------------------------------------------------
__global__ void zero_deg_kernel(int N) {
    int i = blockIdx.x * blockDim.x + threadIdx.x;
    if (i < N) g_deg[i] = 0;
}

__global__ void count_kernel(const int* __restrict__ ei, int E, int N) {
    int i = blockIdx.x * blockDim.x + threadIdx.x;
    int EL = E + N;
    if (i >= EL) return;
    int dst = (i < E) ? ei[E + i] : (i - E);   // self-loops appended
    atomicAdd(&g_deg[dst], 1);
}

__global__ void scan_kernel(int N) {
    __shared__ int wsum[32];
    int tid  = threadIdx.x;              // 1024 threads
    int lane = tid & 31, w = tid >> 5;
    int CH   = (N + 1023) >> 10;
    int base = tid * CH;

    int s = 0;
    for (int k = 0; k < CH; k++) {
        int idx = base + k;
        if (idx < N) s += g_deg[idx];
    }
    int v = s;
    #pragma unroll
    for (int o = 1; o < 32; o <<= 1) {
        int t = __shfl_up_sync(0xffffffffu, v, o);
        if (lane >= o) v += t;
    }
    if (lane == 31) wsum[w] = v;
    __syncthreads();
    if (w == 0) {
        int t = wsum[lane];
        #pragma unroll
        for (int o = 1; o < 32; o <<= 1) {
            int u = __shfl_up_sync(0xffffffffu, t, o);
            if (lane >= o) t += u;
        }
        wsum[lane] = t;
    }
    __syncthreads();
    int excl = v - s + ((w > 0) ? wsum[w - 1] : 0);
    int run  = excl;
    for (int k = 0; k < CH; k++) {
        int idx = base + k;
        if (idx < N) {
            g_off[idx] = run;
            g_cur[idx] = run;
            run += g_deg[idx];
        }
    }
    if (tid == 1023) g_off[N] = wsum[31];
}

__global__ void scatter_kernel(const int* __restrict__ ei, int E, int N) {
    int i = blockIdx.x * blockDim.x + threadIdx.x;
    int EL = E + N;
    if (i >= EL) return;
    int src, dst;
    if (i < E) { src = ei[i]; dst = ei[E + i]; }
    else       { src = i - E; dst = i - E; }
    int p = atomicAdd(&g_cur[dst], 1);
    g_srcs[p] = src;
}

// ---------------- node encoder: h = relu(x @ node_W + node_b) ----------------
__global__ void init_kernel(const float* __restrict__ x,
                            const float* __restrict__ W,
                            const float* __restrict__ b, int N) {
    int n = blockIdx.x;
    int j = threadIdx.x;
    float acc = b[j];
    #pragma unroll
    for (int k = 0; k < NF; k++)
        acc += x[n * NF + k] * W[k * HIDD + j];
    g_h[n * HIDD + j] = fmaxf(acc, 0.f);
}

// ------- fused projection + attention scalars (R3 float version) -------------
__global__ void proj_att_kernel(const float* __restrict__ W,
                                const float* __restrict__ att_s,
                                const float* __restrict__ att_d, int N) {
    __shared__ float sh[RPB * HIDD];     // 16 KB of h rows
    __shared__ float s_as[4][RPB], s_ad[4][RPB];   // per-warp partials
    int tid = threadIdx.x, lane = tid & 31, wrp = tid >> 5;
    int n0 = blockIdx.x * RPB;
    int hy = blockIdx.y;
    int col = hy * 128 + tid;

    // cooperative load of RPB rows of h (float4)
    for (int t = tid; t < RPB * (HIDD / 4); t += 128) {
        int n = n0 + t / (HIDD / 4);
        float4 v = make_float4(0.f, 0.f, 0.f, 0.f);
        if (n < N) v = ((const float4*)g_h)[(size_t)n * (HIDD / 4) + t % (HIDD / 4)];
        ((float4*)sh)[t] = v;
    }
    __syncthreads();

    float acc[RPB];
    #pragma unroll
    for (int i = 0; i < RPB; i++) acc[i] = 0.f;

    #pragma unroll 4
    for (int k4 = 0; k4 < HIDD / 4; k4++) {
        int k = k4 * 4;
        float w0 = W[(k + 0) * HC + col];
        float w1 = W[(k + 1) * HC + col];
        float w2 = W[(k + 2) * HC + col];
        float w3 = W[(k + 3) * HC + col];
        #pragma unroll
        for (int i = 0; i < RPB; i++) {
            float4 s4 = ((const float4*)(sh + i * HIDD))[k4];
            acc[i] += s4.x * w0 + s4.y * w1 + s4.z * w2 + s4.w * w3;
        }
    }

    // store hp
    #pragma unroll
    for (int i = 0; i < RPB; i++) {
        int n = n0 + i;
        if (n < N) g_hp[(size_t)n * HC + col] = acc[i];
    }

    // attention scalars: a_src[n,hy] = sum_j acc[i][j]*att_s[hy][j]
    float asj = att_s[hy * 128 + tid];
    float adj = att_d[hy * 128 + tid];
    #pragma unroll
    for (int i = 0; i < RPB; i++) {
        float vs = acc[i] * asj;
        float vd = acc[i] * adj;
        #pragma unroll
        for (int o = 16; o; o >>= 1) {
            vs += __shfl_xor_sync(0xffffffffu, vs, o);
            vd += __shfl_xor_sync(0xffffffffu, vd, o);
        }
        if (lane == 0) {
            s_as[wrp][i] = vs;
            s_ad[wrp][i] = vd;
        }
    }
    __syncthreads();
    if (tid < RPB && n0 + tid < N) {
        g_asrc[(n0 + tid) * NH + hy] =
            s_as[0][tid] + s_as[1][tid] + s_as[2][tid] + s_as[3][tid];
        g_adst[(n0 + tid) * NH + hy] =
            s_ad[0][tid] + s_ad[1][tid] + s_ad[2][tid] + s_ad[3][tid];
    }
}

// ---------------- fused: softmax + aggregate + head-mean + LN + relu + resid -
// LAST=1 additionally writes h to out[n] and accumulates graph-mean sums.
template <int LAST>
__global__ void agg_kernel(const float* __restrict__ bias,
                           const float* __restrict__ lng,
                           const float* __restrict__ lnb,
                           const int* __restrict__ batch,
                           float* __restrict__ out, int N) {
    int n = blockIdx.x;
    int tid = threadIdx.x, lane = tid & 31, w = tid >> 5;
    __shared__ float s_alpha[CAP * NH];
    __shared__ int   s_src[CAP];
    __shared__ float s_m[NH], s_d[NH];
    __shared__ float s_tr[HC];
    __shared__ float s_r1[NH], s_r2[NH];

    int beg = g_off[n], end = g_off[n + 1];
    int deg = end - beg;
    int cd  = (deg < CAP) ? deg : CAP;

    for (int li = tid; li < cd; li += 128) s_src[li] = g_srcs[beg + li];
    __syncthreads();

    // per-warp (head w) softmax max + sum; cache unnormalized weights
    float ad = g_adst[n * NH + w];
    float mx = -1e30f;
    for (int li = lane; li < deg; li += 32) {
        int s = (li < CAP) ? s_src[li] : g_srcs[beg + li];
        float e = g_asrc[s * NH + w] + ad;
        e = (e > 0.f) ? e : 0.2f * e;
        mx = fmaxf(mx, e);
    }
    #pragma unroll
    for (int o = 16; o; o >>= 1) mx = fmaxf(mx, __shfl_xor_sync(0xffffffffu, mx, o));
    float sum = 0.f;
    for (int li = lane; li < deg; li += 32) {
        int s = (li < CAP) ? s_src[li] : g_srcs[beg + li];
        float e = g_asrc[s * NH + w] + ad;
        e = (e > 0.f) ? e : 0.2f * e;
        float ex = __expf(e - mx);
        sum += ex;
        if (li < CAP) s_alpha[li * NH + w] = ex;
    }
    #pragma unroll
    for (int o = 16; o; o >>= 1) sum += __shfl_xor_sync(0xffffffffu, sum, o);
    if (lane == 0) { s_m[w] = mx; s_d[w] = sum; }
    __syncthreads();

    // aggregate: thread tid owns flat channels 4*tid..4*tid+3 (head w,
    // channels 4*lane..4*lane+3). One LDG.128 per thread per edge.
    const float* base = g_hp + 4 * tid;
    float ax = 0.f, ay = 0.f, az = 0.f, aw = 0.f;
    int li = 0;
    for (; li + 2 <= cd; li += 2) {
        int s0 = s_src[li], s1 = s_src[li + 1];
        float4 r0 = *(const float4*)(base + (size_t)s0 * HC);
        float4 r1 = *(const float4*)(base + (size_t)s1 * HC);
        float w0 = s_alpha[li * NH + w];
        float w1 = s_alpha[(li + 1) * NH + w];
        ax += w0 * r0.x + w1 * r1.x;
        ay += w0 * r0.y + w1 * r1.y;
        az += w0 * r0.z + w1 * r1.z;
        aw += w0 * r0.w + w1 * r1.w;
    }
    if (li < cd) {
        int s0 = s_src[li];
        float4 r0 = *(const float4*)(base + (size_t)s0 * HC);
        float w0 = s_alpha[li * NH + w];
        ax += w0 * r0.x; ay += w0 * r0.y; az += w0 * r0.z; aw += w0 * r0.w;
    }
    // rare fallback: in-degree beyond CAP, recompute ex on the fly
    for (int i2 = beg + CAP; i2 < end; ++i2) {
        int s = g_srcs[i2];
        float e = g_asrc[s * NH + w] + ad;
        e = (e > 0.f) ? e : 0.2f * e;
        float ex = __expf(e - s_m[w]);
        float4 r0 = *(const float4*)(base + (size_t)s * HC);
        ax += ex * r0.x; ay += ex * r0.y; az += ex * r0.z; aw += ex * r0.w;
    }

    float inv = 1.f / (s_d[w] + 1e-16f);
    float4 o4 = make_float4(ax * inv, ay * inv, az * inv, aw * inv);
    ((float4*)s_tr)[tid] = o4;
    __syncthreads();

    // head mean (transpose via shared) + bias
    int c = tid;
    float v = 0.25f * (s_tr[c] + s_tr[128 + c] + s_tr[256 + c] + s_tr[384 + c])
              + bias[c];

    // LayerNorm over 128 channels
    float t = v;
    #pragma unroll
    for (int o = 16; o; o >>= 1) t += __shfl_xor_sync(0xffffffffu, t, o);
    if (lane == 0) s_r1[w] = t;
    __syncthreads();
    float mu = (s_r1[0] + s_r1[1] + s_r1[2] + s_r1[3]) * (1.f / 128.f);
    float dv = v - mu;
    float t2 = dv * dv;
    #pragma unroll
    for (int o = 16; o; o >>= 1) t2 += __shfl_xor_sync(0xffffffffu, t2, o);
    if (lane == 0) s_r2[w] = t2;
    __syncthreads();
    float var = (s_r2[0] + s_r2[1] + s_r2[2] + s_r2[3]) * (1.f / 128.f);
    float y = dv * rsqrtf(var + 1e-5f) * lng[c] + lnb[c];

    float hn = fmaxf(y, 0.f) + g_h[n * HIDD + c];
    if (LAST) {
        out[n * HIDD + c] = hn;                        // h copy
        int b = batch[n];
        atomicAdd(&out[(size_t)N * HIDD + b * HIDD + c], hn);
        if (c == 0) atomicAdd(&g_cnt[b], 1);
    } else {
        g_h[n * HIDD + c] = hn;
    }
}

// ---------------- pooling ----------------------------------------------------
__global__ void zero_pool_kernel(float* __restrict__ out, int N, int B) {
    int i = blockIdx.x * blockDim.x + threadIdx.x;
    if (i < B * HIDD) out[N * HIDD + i] = 0.f;
    if (i < B) g_cnt[i] = 0;
}

__global__ void pool_div_kernel(float* __restrict__ out, int N) {
    int b = blockIdx.x;
    int j = threadIdx.x;
    float c = (float)max(g_cnt[b], 1);
    out[N * HIDD + b * HIDD + j] *= (1.f / c);
}

// ---------------- launch -----------------------------------------------------
extern "C" void kernel_launch(void* const* d_in, const int* in_sizes, int n_in,
                              void* d_out, int out_size) {
    const float* x        = (const float*)d_in[0];
    const int*   ei       = (const int*)d_in[1];   // [2,E] int32
    const int*   batch    = (const int*)d_in[2];
    const float* node_W   = (const float*)d_in[3];
    const float* node_b   = (const float*)d_in[4];
    const float* Ws       = (const float*)d_in[5];
    const float* att_srcs = (const float*)d_in[6];
    const float* att_dsts = (const float*)d_in[7];
    const float* biases   = (const float*)d_in[8];
    const float* ln_gs    = (const float*)d_in[9];
    const float* ln_bs    = (const float*)d_in[10];
    float* out = (float*)d_out;

    int N  = in_sizes[0] / NF;
    int E  = in_sizes[1] / 2;
    int B  = out_size / HIDD - N;
    int L  = in_sizes[5] / (HIDD * HC);
    int EL = E + N;

    // fork-join: CSR build + pool zeroing on a side stream, overlapped with
    // init + first projection on the main (captured) stream.
    static cudaStream_t s2 = nullptr;
    static cudaEvent_t eFork = nullptr, eJoin = nullptr;
    if (!s2) {
        cudaStreamCreateWithFlags(&s2, cudaStreamNonBlocking);
        cudaEventCreateWithFlags(&eFork, cudaEventDisableTiming);
        cudaEventCreateWithFlags(&eJoin, cudaEventDisableTiming);
    }

    cudaEventRecord(eFork, 0);
    cudaStreamWaitEvent(s2, eFork, 0);

    zero_deg_kernel<<<(N + 255) / 256, 256, 0, s2>>>(N);
    count_kernel<<<(EL + 255) / 256, 256, 0, s2>>>(ei, E, N);
    scan_kernel<<<1, 1024, 0, s2>>>(N);
    scatter_kernel<<<(EL + 255) / 256, 256, 0, s2>>>(ei, E, N);
    zero_pool_kernel<<<(B * HIDD + 255) / 256, 256, 0, s2>>>(out, N, B);
    cudaEventRecord(eJoin, s2);

    init_kernel<<<N, HIDD>>>(x, node_W, node_b, N);
    proj_att_kernel<<<dim3((N + RPB - 1) / RPB, NH), 128>>>(
        Ws, att_srcs, att_dsts, N);

    cudaStreamWaitEvent(0, eJoin, 0);

    for (int l = 0; l < L; l++) {
        if (l > 0)
            proj_att_kernel<<<dim3((N + RPB - 1) / RPB, NH), 128>>>(
                Ws + (size_t)l * HIDD * HC,
                att_srcs + l * NH * 128, att_dsts + l * NH * 128, N);
        if (l < L - 1)
            agg_kernel<0><<<N, 128>>>(biases + l * HIDD, ln_gs + l * HIDD,
                                      ln_bs + l * HIDD, batch, out, N);
        else
            agg_kernel<1><<<N, 128>>>(biases + l * HIDD, ln_gs + l * HIDD,
                                      ln_bs + l * HIDD, batch, out, N);
    }

    pool_div_kernel<<<B, HIDD>>>(out, N);
}